// round 9
// baseline (speedup 1.0000x reference)
#include <cuda_runtime.h>
#include <cuda_bf16.h>

// Problem: B=500000, F=32, U=48, S=1000, H=24
// Output: concat( out[B,1], new_state[S,48] ) -> float32

#define ULL unsigned long long
#define CAP 4096
#define NCHUNK 4
#define BIN_CTAS 64

__device__ float g_G[1000 * 144];       // state @ gru_rec_kernel
__device__ int   g_winner[1000];        // last (max) row index per slot
__device__ int   g_count[1000];
__device__ int   g_perm[1000 * CAP];    // padded bins

// ---------- packed f32x2 helpers ----------
__device__ __forceinline__ ULL pk2(float lo, float hi) {
    ULL r; asm("mov.b64 %0, {%1, %2};" : "=l"(r) : "f"(lo), "f"(hi)); return r;
}
__device__ __forceinline__ float2 up2(ULL v) {
    float2 r; asm("mov.b64 {%0, %1}, %2;" : "=f"(r.x), "=f"(r.y) : "l"(v)); return r;
}
__device__ __forceinline__ ULL fma2(ULL a, ULL b, ULL c) {
    ULL d; asm("fma.rn.f32x2 %0, %1, %2, %3;" : "=l"(d) : "l"(a), "l"(b), "l"(c)); return d;
}
__device__ __forceinline__ float hsum2(ULL v) { float2 f = up2(v); return f.x + f.y; }

__device__ __forceinline__ float sigmoidf(float x) {
    return __fdividef(1.0f, 1.0f + __expf(-x));
}
__device__ __forceinline__ float tanh_fast(float x) {
    return fmaf(2.0f, __fdividef(1.0f, 1.0f + __expf(-2.0f * x)), -1.0f);
}

// ---------- kernel 0: fused prep (blocks 0..999) + binning (blocks 1000..1063) ----------
__global__ void __launch_bounds__(256)
setup_kernel(const float* __restrict__ state,
             const float* __restrict__ Urec,
             float* __restrict__ out_state,
             const int* __restrict__ ids, int B) {
    const int tid = threadIdx.x;
    if (blockIdx.x < 1000) {
        const int s = blockIdx.x;
        __shared__ float hs[48];
        if (tid < 48) {
            float v = state[s * 48 + tid];
            hs[tid] = v;
            out_state[s * 48 + tid] = v;
        }
        if (tid == 0) { g_winner[s] = -1; g_count[s] = 0; }
        __syncthreads();
        if (tid < 144) {
            float acc = 0.0f;
            #pragma unroll
            for (int u = 0; u < 48; u++)
                acc = fmaf(hs[u], Urec[u * 144 + tid], acc);
            g_G[s * 144 + tid] = acc;
        }
    } else {
        __shared__ int lcnt[1000];
        __shared__ int lmax[1000];
        __shared__ int lbase[1000];
        const int cta = blockIdx.x - 1000;
        const int per = (B + BIN_CTAS - 1) / BIN_CTAS;
        const int lo = cta * per;
        const int hi = min(B, lo + per);

        for (int s = tid; s < 1000; s += 256) { lcnt[s] = 0; lmax[s] = -1; }
        __syncthreads();

        for (int b = lo + tid; b < hi; b += 256) {
            int id = ids[b];
            atomicAdd(&lcnt[id], 1);
            atomicMax(&lmax[id], b);
        }
        __syncthreads();

        for (int s = tid; s < 1000; s += 256) {
            int c = lcnt[s];
            if (c > 0) {
                lbase[s] = atomicAdd(&g_count[s], c);
                atomicMax(&g_winner[s], lmax[s]);
                lcnt[s] = 0;
            }
        }
        __syncthreads();

        for (int b = lo + tid; b < hi; b += 256) {
            int id = ids[b];
            int off = atomicAdd(&lcnt[id], 1);
            int pos = lbase[id] + off;
            if (pos < CAP) g_perm[id * CAP + pos] = b;
        }
    }
}

// ---------- kernel 1: main fused GRU + MLP head, 2 rows per thread ----------
__global__ void __launch_bounds__(96)
main_kernel(const float* __restrict__ inputs,
            const float* __restrict__ state,
            const float* __restrict__ Wk,      // [32,144]
            const float* __restrict__ gbias,   // [144]
            const float* __restrict__ Dw,      // [80,24]
            const float* __restrict__ Db,      // [24]
            const float* __restrict__ Ow,      // [24]
            const float* __restrict__ Ob,      // [1]
            float* __restrict__ out,           // [B]
            float* __restrict__ out_state) {   // [S,48]
    __shared__ __align__(16) float sW[144 * 32];   // sW[j*32+f]  = Wk[f][j]
    __shared__ __align__(16) float sDx[24 * 32];   // sDx[j*32+f] = Dw[f][j]     (x part, j-major)
    __shared__ __align__(16) float sDh[48 * 24];   // sDh[u*24+j] = Dw[32+u][j]  (h part, u-major)
    __shared__ float sB[144];
    __shared__ float sG[144];
    __shared__ float sh[48];
    __shared__ float sDb[24];
    __shared__ float sOw[24];
    __shared__ float sOb;

    const int tid   = threadIdx.x;
    const int s     = blockIdx.x >> 2;             // slot
    const int chunk = blockIdx.x & (NCHUNK - 1);

    for (int i = tid; i < 144 * 32; i += 96) {
        int j = i >> 5, f = i & 31;
        sW[i] = Wk[f * 144 + j];
    }
    for (int i = tid; i < 24 * 32; i += 96) {
        int j = i >> 5, f = i & 31;
        sDx[i] = Dw[f * 24 + j];
    }
    for (int i = tid; i < 48 * 24; i += 96) {
        int u = i / 24, j = i - u * 24;
        sDh[i] = Dw[(32 + u) * 24 + j];
    }
    for (int i = tid; i < 144; i += 96) { sB[i] = gbias[i]; sG[i] = g_G[s * 144 + i]; }
    if (tid < 48) sh[tid] = state[s * 48 + tid];
    if (tid < 24) { sDb[tid] = Db[tid]; sOw[tid] = Ow[tid]; }
    if (tid == 0) sOb = Ob[0];
    __syncthreads();

    const int cnt    = min(g_count[s], CAP);
    const int winner = g_winner[s];
    const int* bin   = g_perm + s * CAP;
    const int stride = NCHUNK * 96;                // 384

    for (int i = chunk * 96 + tid; i < cnt; i += 2 * stride) {
        const int  i1 = i + stride;
        const bool v1 = (i1 < cnt);
        const int  b0 = bin[i];
        const int  b1 = v1 ? bin[i1] : b0;

        // load both x rows as packed pairs
        ULL x0[16], x1[16];
        {
            const float4* xr0 = (const float4*)(inputs + (size_t)b0 * 32);
            const float4* xr1 = (const float4*)(inputs + (size_t)b1 * 32);
            #pragma unroll
            for (int k = 0; k < 8; k++) {
                float4 a = xr0[k], b = xr1[k];
                x0[2 * k] = pk2(a.x, a.y); x0[2 * k + 1] = pk2(a.z, a.w);
                x1[2 * k] = pk2(b.x, b.y); x1[2 * k + 1] = pk2(b.z, b.w);
            }
        }

        // ---- dense head x-part: a0/a1[m] = (hid[2m], hid[2m+1]) pre-activation ----
        ULL a0[12], a1[12];
        #pragma unroll
        for (int m = 0; m < 12; m++) {
            float h0j[2], h1j[2];
            #pragma unroll
            for (int p = 0; p < 2; p++) {
                const int j = 2 * m + p;
                const ulonglong2* dj = (const ulonglong2*)(sDx + 32 * j);
                ULL t0 = 0ULL, t1 = 0ULL;
                #pragma unroll
                for (int k = 0; k < 8; k++) {
                    ulonglong2 w = dj[k];
                    t0 = fma2(x0[2 * k], w.x, t0); t0 = fma2(x0[2 * k + 1], w.y, t0);
                    t1 = fma2(x1[2 * k], w.x, t1); t1 = fma2(x1[2 * k + 1], w.y, t1);
                }
                h0j[p] = hsum2(t0); h1j[p] = hsum2(t1);
            }
            a0[m] = pk2(h0j[0], h0j[1]);
            a1[m] = pk2(h1j[0], h1j[1]);
        }

        // ---- GRU (rolled over q): weights shared across both rows; fold h on the fly ----
        const bool w0 = (b0 == winner);
        const bool w1 = v1 && (b1 == winner);
        for (int q = 0; q < 12; q++) {
            #pragma unroll
            for (int p = 0; p < 4; p++) {
                const int u = 4 * q + p;
                const ulonglong2* wz = (const ulonglong2*)(sW + 32 * u);
                const ulonglong2* wr = (const ulonglong2*)(sW + 32 * (48 + u));
                const ulonglong2* wh = (const ulonglong2*)(sW + 32 * (96 + u));
                ULL az0 = 0ULL, ar0 = 0ULL, ah0 = 0ULL;
                ULL az1 = 0ULL, ar1 = 0ULL, ah1 = 0ULL;
                #pragma unroll
                for (int k = 0; k < 8; k++) {
                    ulonglong2 a = wz[k], c = wr[k], e = wh[k];
                    az0 = fma2(x0[2 * k], a.x, az0); az0 = fma2(x0[2 * k + 1], a.y, az0);
                    az1 = fma2(x1[2 * k], a.x, az1); az1 = fma2(x1[2 * k + 1], a.y, az1);
                    ar0 = fma2(x0[2 * k], c.x, ar0); ar0 = fma2(x0[2 * k + 1], c.y, ar0);
                    ar1 = fma2(x1[2 * k], c.x, ar1); ar1 = fma2(x1[2 * k + 1], c.y, ar1);
                    ah0 = fma2(x0[2 * k], e.x, ah0); ah0 = fma2(x0[2 * k + 1], e.y, ah0);
                    ah1 = fma2(x1[2 * k], e.x, ah1); ah1 = fma2(x1[2 * k + 1], e.y, ah1);
                }
                const float bz = sB[u] + sG[u];
                const float br = sB[48 + u] + sG[48 + u];
                const float bh = sB[96 + u];
                const float gh_rec = sG[96 + u];
                const float hprev = sh[u];

                float z0 = sigmoidf(hsum2(az0) + bz);
                float r0 = sigmoidf(hsum2(ar0) + br);
                float hc0 = tanh_fast(fmaf(r0, gh_rec, hsum2(ah0) + bh));
                float h0 = z0 * hprev + (1.0f - z0) * hc0;

                float z1 = sigmoidf(hsum2(az1) + bz);
                float r1 = sigmoidf(hsum2(ar1) + br);
                float hc1 = tanh_fast(fmaf(r1, gh_rec, hsum2(ah1) + bh));
                float h1 = z1 * hprev + (1.0f - z1) * hc1;

                if (w0) out_state[s * 48 + u] = h0;
                if (w1) out_state[s * 48 + u] = h1;

                // fold h[u] into the 24 head accumulators (weights shared)
                ULL hb0 = pk2(h0, h0), hb1 = pk2(h1, h1);
                const ulonglong2* dr = (const ulonglong2*)(sDh + 24 * u);
                #pragma unroll
                for (int m = 0; m < 6; m++) {
                    ulonglong2 w = dr[m];
                    a0[2 * m]     = fma2(hb0, w.x, a0[2 * m]);
                    a0[2 * m + 1] = fma2(hb0, w.y, a0[2 * m + 1]);
                    a1[2 * m]     = fma2(hb1, w.x, a1[2 * m]);
                    a1[2 * m + 1] = fma2(hb1, w.y, a1[2 * m + 1]);
                }
            }
        }

        // ---- finish head: bias, relu, output dot, sigmoid ----
        float o0 = sOb, o1 = sOb;
        #pragma unroll
        for (int m = 0; m < 12; m++) {
            float2 t0 = up2(a0[m]), t1 = up2(a1[m]);
            float d0 = sDb[2 * m], d1 = sDb[2 * m + 1];
            float w0c = sOw[2 * m], w1c = sOw[2 * m + 1];
            o0 = fmaf(fmaxf(t0.x + d0, 0.0f), w0c, o0);
            o0 = fmaf(fmaxf(t0.y + d1, 0.0f), w1c, o0);
            o1 = fmaf(fmaxf(t1.x + d0, 0.0f), w0c, o1);
            o1 = fmaf(fmaxf(t1.y + d1, 0.0f), w1c, o1);
        }
        out[b0] = sigmoidf(o0);
        if (v1) out[b1] = sigmoidf(o1);
    }
}

extern "C" void kernel_launch(void* const* d_in, const int* in_sizes, int n_in,
                              void* d_out, int out_size) {
    const float* inputs = (const float*)d_in[0];
    const int*   ids    = (const int*)d_in[1];
    const float* state  = (const float*)d_in[2];
    const float* Wk     = (const float*)d_in[3];
    const float* Urec   = (const float*)d_in[4];
    const float* gbias  = (const float*)d_in[5];
    const float* Dw     = (const float*)d_in[6];
    const float* Db     = (const float*)d_in[7];
    const float* Ow     = (const float*)d_in[8];
    const float* Ob     = (const float*)d_in[9];

    const int B = in_sizes[0] / 32;
    const int S = in_sizes[2] / 48;

    float* out       = (float*)d_out;
    float* out_state = out + B;

    setup_kernel<<<S + BIN_CTAS, 256>>>(state, Urec, out_state, ids, B);
    main_kernel<<<S * NCHUNK, 96>>>(inputs, state, Wk, gbias,
                                    Dw, Db, Ow, Ob, out, out_state);
}